// round 3
// baseline (speedup 1.0000x reference)
#include <cuda_runtime.h>

#define NN 60000
#define EE 1200000
#define DD 64
#define OUTD 192   // K * D

// ---- device scratch (static allocation is the sanctioned workaround) ----
__device__ int   g_deg[NN];
__device__ int   g_rowptr[NN + 1];
__device__ int   g_cursor[NN];
__device__ int   g_col[EE];
__device__ float g_dinv[NN];
__device__ float g_Xs [NN * DD];   // X0 * d^-1/2  (gather source, pass 1)
__device__ float g_X1 [NN * DD];   // raw X1       (needed for X2 recurrence)
__device__ float g_X1s[NN * DD];   // X1 * d^-1/2  (gather source, pass 2)

__global__ void k_zero_deg() {
    int i = blockIdx.x * blockDim.x + threadIdx.x;
    if (i < NN) g_deg[i] = 0;
}

__global__ void k_deg(const int* __restrict__ dst) {
    int e = blockIdx.x * blockDim.x + threadIdx.x;
    if (e < EE) atomicAdd(&g_deg[dst[e]], 1);
}

// Single-block chunked scan: each thread owns a contiguous chunk, block-scans
// the 1024 chunk sums, then writes rowptr/cursor for its chunk.
__global__ void k_scan() {
    const int T = 1024;
    int tid = threadIdx.x;
    int chunk = (NN + T - 1) / T;
    int start = tid * chunk;
    int end = min(start + chunk, NN);
    int sum = 0;
    for (int i = start; i < end; i++) sum += g_deg[i];

    __shared__ int sh[T];
    sh[tid] = sum;
    __syncthreads();
    for (int off = 1; off < T; off <<= 1) {
        int v = (tid >= off) ? sh[tid - off] : 0;
        __syncthreads();
        sh[tid] += v;
        __syncthreads();
    }
    int run = sh[tid] - sum;   // exclusive prefix of this chunk
    for (int i = start; i < end; i++) {
        g_rowptr[i] = run;
        g_cursor[i] = run;
        run += g_deg[i];
    }
    if (tid == T - 1) g_rowptr[NN] = run;
}

// dinv, Xs = feat * dinv, out[:, 0:64] = relu(feat)
__global__ void k_prep(const float* __restrict__ feat, float* __restrict__ out) {
    int t = blockIdx.x * blockDim.x + threadIdx.x;
    if (t >= NN * 16) return;
    int i = t >> 4;
    int c = (t & 15) << 2;
    float dinv = rsqrtf(fmaxf((float)g_deg[i], 1.0f));
    if ((t & 15) == 0) g_dinv[i] = dinv;
    float4 f = *(const float4*)(feat + (size_t)i * DD + c);
    float4 xs = make_float4(f.x * dinv, f.y * dinv, f.z * dinv, f.w * dinv);
    *(float4*)(g_Xs + (size_t)i * DD + c) = xs;
    float4 r = make_float4(fmaxf(f.x, 0.f), fmaxf(f.y, 0.f),
                           fmaxf(f.z, 0.f), fmaxf(f.w, 0.f));
    *(float4*)(out + (size_t)i * OUTD + c) = r;
}

__global__ void k_fill(const int* __restrict__ src, const int* __restrict__ dst) {
    int e = blockIdx.x * blockDim.x + threadIdx.x;
    if (e < EE) {
        int p = atomicAdd(&g_cursor[dst[e]], 1);
        g_col[p] = src[e];
    }
}

// pass 1: h = dinv * sum(Xs[col]); X1 = -rn*h + (rn-1)*X0
// writes g_X1 (raw), g_X1s (scaled), out[:, 64:128] = relu(X1)
__global__ void k_spmm1(const float* __restrict__ feat,
                        const float* __restrict__ lambda_max,
                        float* __restrict__ out) {
    int w = (blockIdx.x * blockDim.x + threadIdx.x) >> 5;
    int lane = threadIdx.x & 31;
    if (w >= NN) return;
    int beg = g_rowptr[w];
    int end = g_rowptr[w + 1];
    float ax = 0.f, ay = 0.f;
    for (int e = beg; e < end; e++) {
        int s = g_col[e];
        float2 v = *(const float2*)(g_Xs + (size_t)s * DD + lane * 2);
        ax += v.x; ay += v.y;
    }
    float dinv = g_dinv[w];
    float rn = 2.0f / lambda_max[0];
    float2 x0 = *(const float2*)(feat + (size_t)w * DD + lane * 2);
    float x1x = -rn * (ax * dinv) + (rn - 1.f) * x0.x;
    float x1y = -rn * (ay * dinv) + (rn - 1.f) * x0.y;
    *(float2*)(g_X1  + (size_t)w * DD + lane * 2) = make_float2(x1x, x1y);
    *(float2*)(g_X1s + (size_t)w * DD + lane * 2) = make_float2(x1x * dinv, x1y * dinv);
    *(float2*)(out + (size_t)w * OUTD + DD + lane * 2) =
        make_float2(fmaxf(x1x, 0.f), fmaxf(x1y, 0.f));
}

// pass 2: h2 = dinv * sum(X1s[col]); X2 = -2*rn*h2 + 2*(rn-1)*X1 - X0
// writes out[:, 128:192] = relu(X2)
__global__ void k_spmm2(const float* __restrict__ feat,
                        const float* __restrict__ lambda_max,
                        float* __restrict__ out) {
    int w = (blockIdx.x * blockDim.x + threadIdx.x) >> 5;
    int lane = threadIdx.x & 31;
    if (w >= NN) return;
    int beg = g_rowptr[w];
    int end = g_rowptr[w + 1];
    float ax = 0.f, ay = 0.f;
    for (int e = beg; e < end; e++) {
        int s = g_col[e];
        float2 v = *(const float2*)(g_X1s + (size_t)s * DD + lane * 2);
        ax += v.x; ay += v.y;
    }
    float dinv = g_dinv[w];
    float rn = 2.0f / lambda_max[0];
    float2 x0 = *(const float2*)(feat + (size_t)w * DD + lane * 2);
    float2 x1 = *(const float2*)(g_X1 + (size_t)w * DD + lane * 2);
    float x2x = -2.f * rn * (ax * dinv) + 2.f * (rn - 1.f) * x1.x - x0.x;
    float x2y = -2.f * rn * (ay * dinv) + 2.f * (rn - 1.f) * x1.y - x0.y;
    *(float2*)(out + (size_t)w * OUTD + 2 * DD + lane * 2) =
        make_float2(fmaxf(x2x, 0.f), fmaxf(x2y, 0.f));
}

extern "C" void kernel_launch(void* const* d_in, const int* in_sizes, int n_in,
                              void* d_out, int out_size) {
    const float* feat       = (const float*)d_in[0];
    const int*   src        = (const int*)d_in[1];
    const int*   dst        = (const int*)d_in[2];
    const float* lambda_max = (const float*)d_in[3];
    float* out = (float*)d_out;

    const int TB = 256;
    k_zero_deg<<<(NN + TB - 1) / TB, TB>>>();
    k_deg<<<(EE + TB - 1) / TB, TB>>>(dst);
    k_scan<<<1, 1024>>>();
    k_prep<<<(NN * 16 + TB - 1) / TB, TB>>>(feat, out);
    k_fill<<<(EE + TB - 1) / TB, TB>>>(src, dst);
    k_spmm1<<<(NN * 32 + TB - 1) / TB, TB>>>(feat, lambda_max, out);
    k_spmm2<<<(NN * 32 + TB - 1) / TB, TB>>>(feat, lambda_max, out);
}

// round 5
// speedup vs baseline: 1.5144x; 1.5144x over previous
#include <cuda_runtime.h>

#define NN 60000
#define EE 1200000
#define DD 64
#define OUTD 192   // K * D

// ---- device scratch ----
__device__ int   g_deg[NN];
__device__ int   g_rowptr[NN + 1];
__device__ int   g_cursor[NN];
__device__ int   g_col[EE];
__device__ float g_dinv[NN];    // d^-1/2
__device__ float g_rdinv[NN];   // d^+1/2  (to undo scaling in pass 2)
__device__ float g_Xs [NN * DD];   // X0 * d^-1/2  (gather source, pass 1)
__device__ float g_X1s[NN * DD];   // X1 * d^-1/2  (gather source, pass 2)

__global__ void k_zero_deg() {
    int i = blockIdx.x * blockDim.x + threadIdx.x;
    if (i < NN) g_deg[i] = 0;
}

__global__ void k_deg(const int* __restrict__ dst) {
    int e = blockIdx.x * blockDim.x + threadIdx.x;
    if (e < EE) atomicAdd(&g_deg[dst[e]], 1);
}

// Single-block chunked scan, int4-vectorized. chunk=60 (4-aligned, 1000*60=NN).
__global__ void k_scan() {
    const int T = 1024;
    const int CH = 60;
    int tid = threadIdx.x;
    int start = tid * CH;
    int sum = 0;
    if (start < NN) {
        const int4* p = (const int4*)(g_deg + start);
        #pragma unroll
        for (int i = 0; i < CH / 4; i++) {
            int4 v = p[i];
            sum += v.x + v.y + v.z + v.w;
        }
    }
    __shared__ int sh[T];
    sh[tid] = sum;
    __syncthreads();
    for (int off = 1; off < T; off <<= 1) {
        int v = (tid >= off) ? sh[tid - off] : 0;
        __syncthreads();
        sh[tid] += v;
        __syncthreads();
    }
    int run = sh[tid] - sum;   // exclusive prefix of this chunk
    if (start < NN) {
        const int4* p = (const int4*)(g_deg + start);
        int4* rp = (int4*)(g_rowptr + start);
        int4* cp = (int4*)(g_cursor + start);
        #pragma unroll
        for (int i = 0; i < CH / 4; i++) {
            int4 d = p[i];
            int4 r;
            r.x = run;
            r.y = r.x + d.x;
            r.z = r.y + d.y;
            r.w = r.z + d.z;
            run = r.w + d.w;
            rp[i] = r;
            cp[i] = r;
        }
    }
    if (tid == T - 1) g_rowptr[NN] = run;
}

// 4 threads per node, 4 float4 each: dinv/rdinv, Xs = feat*dinv, out[:,0:64]=relu(feat)
__global__ void k_prep(const float* __restrict__ feat, float* __restrict__ out) {
    int t = blockIdx.x * blockDim.x + threadIdx.x;
    if (t >= NN * 4) return;
    int i = t >> 2;
    int c0 = (t & 3) << 4;   // 0,16,32,48
    float dinv = rsqrtf(fmaxf((float)g_deg[i], 1.0f));
    if ((t & 3) == 0) {
        g_dinv[i] = dinv;
        g_rdinv[i] = 1.0f / dinv;
    }
    const float4* fp = (const float4*)(feat + (size_t)i * DD + c0);
    float4* xp = (float4*)(g_Xs + (size_t)i * DD + c0);
    float4* op = (float4*)(out + (size_t)i * OUTD + c0);
    float4 f[4];
    #pragma unroll
    for (int j = 0; j < 4; j++) f[j] = fp[j];
    #pragma unroll
    for (int j = 0; j < 4; j++) {
        float4 v = f[j];
        xp[j] = make_float4(v.x * dinv, v.y * dinv, v.z * dinv, v.w * dinv);
        op[j] = make_float4(fmaxf(v.x, 0.f), fmaxf(v.y, 0.f),
                            fmaxf(v.z, 0.f), fmaxf(v.w, 0.f));
    }
}

__global__ void k_fill(const int* __restrict__ src, const int* __restrict__ dst) {
    int e = blockIdx.x * blockDim.x + threadIdx.x;
    if (e < EE) {
        int p = atomicAdd(&g_cursor[dst[e]], 1);
        g_col[p] = src[e];
    }
}

// Warp gathers sum of table rows for node w.
// Half-warps handle alternating edges; lane&15 selects a float4 (16 features' worth).
// Result: lanes 0-15 hold the full sum for features [4*fl, 4*fl+4).
__device__ __forceinline__ float4 gather_sum(const float* __restrict__ table,
                                             int beg, int end, int lane) {
    int half = lane >> 4;
    int fl = lane & 15;
    float4 acc = make_float4(0.f, 0.f, 0.f, 0.f);
    int e = beg + half;
    // 4 edges per half-warp per iteration: batch index loads for MLP
    for (; e + 6 < end; e += 8) {
        int s0 = g_col[e];
        int s1 = g_col[e + 2];
        int s2 = g_col[e + 4];
        int s3 = g_col[e + 6];
        float4 v0 = *(const float4*)(table + (size_t)s0 * DD + fl * 4);
        float4 v1 = *(const float4*)(table + (size_t)s1 * DD + fl * 4);
        float4 v2 = *(const float4*)(table + (size_t)s2 * DD + fl * 4);
        float4 v3 = *(const float4*)(table + (size_t)s3 * DD + fl * 4);
        acc.x += v0.x + v1.x + v2.x + v3.x;
        acc.y += v0.y + v1.y + v2.y + v3.y;
        acc.z += v0.z + v1.z + v2.z + v3.z;
        acc.w += v0.w + v1.w + v2.w + v3.w;
    }
    for (; e < end; e += 2) {
        int s = g_col[e];
        float4 v = *(const float4*)(table + (size_t)s * DD + fl * 4);
        acc.x += v.x; acc.y += v.y; acc.z += v.z; acc.w += v.w;
    }
    // merge the two half-warps (different edge subsets, same features)
    acc.x += __shfl_xor_sync(0xFFFFFFFF, acc.x, 16);
    acc.y += __shfl_xor_sync(0xFFFFFFFF, acc.y, 16);
    acc.z += __shfl_xor_sync(0xFFFFFFFF, acc.z, 16);
    acc.w += __shfl_xor_sync(0xFFFFFFFF, acc.w, 16);
    return acc;
}

// pass 1: h = dinv * sum(Xs[col]); X1 = -rn*h + (rn-1)*X0
// writes g_X1s (scaled), out[:, 64:128] = relu(X1)
__global__ void k_spmm1(const float* __restrict__ feat,
                        const float* __restrict__ lambda_max,
                        float* __restrict__ out) {
    int w = (blockIdx.x * blockDim.x + threadIdx.x) >> 5;
    int lane = threadIdx.x & 31;
    if (w >= NN) return;
    int beg = g_rowptr[w];
    int end = g_rowptr[w + 1];
    float4 acc = gather_sum(g_Xs, beg, end, lane);
    if (lane < 16) {
        float dinv = g_dinv[w];
        float rn = 2.0f / lambda_max[0];
        float a = -rn * dinv;      // h contribution coefficient
        float b = rn - 1.0f;
        float4 x0 = *(const float4*)(feat + (size_t)w * DD + lane * 4);
        float4 x1;
        x1.x = a * acc.x + b * x0.x;
        x1.y = a * acc.y + b * x0.y;
        x1.z = a * acc.z + b * x0.z;
        x1.w = a * acc.w + b * x0.w;
        *(float4*)(g_X1s + (size_t)w * DD + lane * 4) =
            make_float4(x1.x * dinv, x1.y * dinv, x1.z * dinv, x1.w * dinv);
        *(float4*)(out + (size_t)w * OUTD + DD + lane * 4) =
            make_float4(fmaxf(x1.x, 0.f), fmaxf(x1.y, 0.f),
                        fmaxf(x1.z, 0.f), fmaxf(x1.w, 0.f));
    }
}

// pass 2: h2 = dinv * sum(X1s[col]); X1 = X1s * rdinv;
// X2 = -2*rn*h2 + 2*(rn-1)*X1 - X0 ; out[:, 128:192] = relu(X2)
__global__ void k_spmm2(const float* __restrict__ feat,
                        const float* __restrict__ lambda_max,
                        float* __restrict__ out) {
    int w = (blockIdx.x * blockDim.x + threadIdx.x) >> 5;
    int lane = threadIdx.x & 31;
    if (w >= NN) return;
    int beg = g_rowptr[w];
    int end = g_rowptr[w + 1];
    float4 acc = gather_sum(g_X1s, beg, end, lane);
    if (lane < 16) {
        float dinv = g_dinv[w];
        float rdinv = g_rdinv[w];
        float rn = 2.0f / lambda_max[0];
        float a = -2.0f * rn * dinv;
        float b = 2.0f * (rn - 1.0f) * rdinv;   // applied to stored X1s -> raw X1
        float4 x0 = *(const float4*)(feat + (size_t)w * DD + lane * 4);
        float4 x1s = *(const float4*)(g_X1s + (size_t)w * DD + lane * 4);
        float4 x2;
        x2.x = a * acc.x + b * x1s.x - x0.x;
        x2.y = a * acc.y + b * x1s.y - x0.y;
        x2.z = a * acc.z + b * x1s.z - x0.z;
        x2.w = a * acc.w + b * x1s.w - x0.w;
        *(float4*)(out + (size_t)w * OUTD + 2 * DD + lane * 4) =
            make_float4(fmaxf(x2.x, 0.f), fmaxf(x2.y, 0.f),
                        fmaxf(x2.z, 0.f), fmaxf(x2.w, 0.f));
    }
}

extern "C" void kernel_launch(void* const* d_in, const int* in_sizes, int n_in,
                              void* d_out, int out_size) {
    const float* feat       = (const float*)d_in[0];
    const int*   src        = (const int*)d_in[1];
    const int*   dst        = (const int*)d_in[2];
    const float* lambda_max = (const float*)d_in[3];
    float* out = (float*)d_out;

    const int TB = 256;
    k_zero_deg<<<(NN + TB - 1) / TB, TB>>>();
    k_deg<<<(EE + TB - 1) / TB, TB>>>(dst);
    k_scan<<<1, 1024>>>();
    k_prep<<<(NN * 4 + TB - 1) / TB, TB>>>(feat, out);
    k_fill<<<(EE + TB - 1) / TB, TB>>>(src, dst);
    k_spmm1<<<(NN * 32 + TB - 1) / TB, TB>>>(feat, lambda_max, out);
    k_spmm2<<<(NN * 32 + TB - 1) / TB, TB>>>(feat, lambda_max, out);
}

// round 10
// speedup vs baseline: 1.6878x; 1.1145x over previous
#include <cuda_runtime.h>
#include <cuda_fp16.h>

#define NN 60000
#define EE 1200000
#define DD 64
#define OUTD 192   // K * D

// ---- device scratch ----
__device__ int    g_deg[NN];
__device__ int    g_rowptr[NN + 1];
__device__ int    g_cursor[NN];
__device__ int    g_col[EE];
__device__ float  g_dinv[NN];            // d^-1/2
__device__ __half g_Xs_h [NN * DD];      // fp16: X0 * d^-1/2   (gather src, pass 1)
__device__ __half g_X1s_h[NN * DD];      // fp16: X1 * d^-1/2   (gather src, pass 2)
__device__ float  g_X1  [NN * DD];       // fp32: raw X1 (for exact recurrence term)

// bit-reinterpret helpers (no-op in SASS)
__device__ __forceinline__ unsigned h2_bits(__half2 h) {
    return *(unsigned*)&h;
}
__device__ __forceinline__ float2 bits_f2(unsigned u) {
    __half2 h = *(__half2*)&u;
    return __half22float2(h);
}

__global__ void k_zero_deg() {
    int i = blockIdx.x * blockDim.x + threadIdx.x;
    if (i < NN) g_deg[i] = 0;
}

__global__ void k_deg(const int* __restrict__ dst) {
    int e = blockIdx.x * blockDim.x + threadIdx.x;
    if (e < EE) atomicAdd(&g_deg[dst[e]], 1);
}

// Single-block chunked scan, int4-vectorized. chunk=60 (4-aligned, 1000*60=NN).
__global__ void k_scan() {
    const int T = 1024;
    const int CH = 60;
    int tid = threadIdx.x;
    int start = tid * CH;
    int sum = 0;
    if (start < NN) {
        const int4* p = (const int4*)(g_deg + start);
        #pragma unroll
        for (int i = 0; i < CH / 4; i++) {
            int4 v = p[i];
            sum += v.x + v.y + v.z + v.w;
        }
    }
    __shared__ int sh[T];
    sh[tid] = sum;
    __syncthreads();
    for (int off = 1; off < T; off <<= 1) {
        int v = (tid >= off) ? sh[tid - off] : 0;
        __syncthreads();
        sh[tid] += v;
        __syncthreads();
    }
    int run = sh[tid] - sum;   // exclusive prefix of this chunk
    if (start < NN) {
        const int4* p = (const int4*)(g_deg + start);
        int4* rp = (int4*)(g_rowptr + start);
        int4* cp = (int4*)(g_cursor + start);
        #pragma unroll
        for (int i = 0; i < CH / 4; i++) {
            int4 d = p[i];
            int4 r;
            r.x = run;
            r.y = r.x + d.x;
            r.z = r.y + d.y;
            r.w = r.z + d.z;
            run = r.w + d.w;
            rp[i] = r;
            cp[i] = r;
        }
    }
    if (tid == T - 1) g_rowptr[NN] = run;
}

// 16 threads per node, 1 float4 each: dinv, Xs_h = fp16(feat*dinv), out[:,0:64]=relu(feat)
__global__ void k_prep(const float* __restrict__ feat, float* __restrict__ out) {
    int t = blockIdx.x * blockDim.x + threadIdx.x;
    if (t >= NN * 16) return;
    int i = t >> 4;
    int c = (t & 15) << 2;
    float dinv = rsqrtf(fmaxf((float)g_deg[i], 1.0f));
    if ((t & 15) == 0) g_dinv[i] = dinv;
    float4 f = *(const float4*)(feat + (size_t)i * DD + c);
    __half2 h0 = __float22half2_rn(make_float2(f.x * dinv, f.y * dinv));
    __half2 h1 = __float22half2_rn(make_float2(f.z * dinv, f.w * dinv));
    uint2 packed = make_uint2(h2_bits(h0), h2_bits(h1));
    *(uint2*)((char*)g_Xs_h + (size_t)i * DD * 2 + c * 2) = packed;
    *(float4*)(out + (size_t)i * OUTD + c) =
        make_float4(fmaxf(f.x, 0.f), fmaxf(f.y, 0.f), fmaxf(f.z, 0.f), fmaxf(f.w, 0.f));
}

__global__ void k_fill(const int* __restrict__ src, const int* __restrict__ dst) {
    int e = blockIdx.x * blockDim.x + threadIdx.x;
    if (e < EE) {
        int p = atomicAdd(&g_cursor[dst[e]], 1);
        g_col[p] = src[e];
    }
}

// Warp gathers fp16 rows (128B each) for node w.
// Half-warps handle alternating edges; lane fl in [0,16) loads 4 halfs (8B).
// Result: lanes 0-15 hold fp32 sums for features [4*fl, 4*fl+4).
__device__ __forceinline__ float4 gather_sum_h(const __half* __restrict__ table,
                                               int beg, int end, int lane) {
    int half_id = lane >> 4;
    int fl = lane & 15;
    float ax = 0.f, ay = 0.f, az = 0.f, aw = 0.f;
    const char* base = (const char*)table;
    int e = beg + half_id;
    for (; e + 6 < end; e += 8) {
        int s0 = g_col[e];
        int s1 = g_col[e + 2];
        int s2 = g_col[e + 4];
        int s3 = g_col[e + 6];
        uint2 p0 = *(const uint2*)(base + (size_t)s0 * 128 + fl * 8);
        uint2 p1 = *(const uint2*)(base + (size_t)s1 * 128 + fl * 8);
        uint2 p2 = *(const uint2*)(base + (size_t)s2 * 128 + fl * 8);
        uint2 p3 = *(const uint2*)(base + (size_t)s3 * 128 + fl * 8);
        #pragma unroll
        for (int j = 0; j < 4; j++) {
            uint2 p = (j == 0) ? p0 : (j == 1) ? p1 : (j == 2) ? p2 : p3;
            float2 lo = bits_f2(p.x);
            float2 hi = bits_f2(p.y);
            ax += lo.x; ay += lo.y; az += hi.x; aw += hi.y;
        }
    }
    for (; e < end; e += 2) {
        int s = g_col[e];
        uint2 p = *(const uint2*)(base + (size_t)s * 128 + fl * 8);
        float2 lo = bits_f2(p.x);
        float2 hi = bits_f2(p.y);
        ax += lo.x; ay += lo.y; az += hi.x; aw += hi.y;
    }
    ax += __shfl_xor_sync(0xFFFFFFFF, ax, 16);
    ay += __shfl_xor_sync(0xFFFFFFFF, ay, 16);
    az += __shfl_xor_sync(0xFFFFFFFF, az, 16);
    aw += __shfl_xor_sync(0xFFFFFFFF, aw, 16);
    return make_float4(ax, ay, az, aw);
}

// pass 1: h = dinv * sum(Xs[col]); X1 = -rn*h + (rn-1)*X0
// writes g_X1 (fp32), g_X1s_h (fp16 scaled), out[:, 64:128] = relu(X1)
__global__ void k_spmm1(const float* __restrict__ feat,
                        const float* __restrict__ lambda_max,
                        float* __restrict__ out) {
    int w = (blockIdx.x * blockDim.x + threadIdx.x) >> 5;
    int lane = threadIdx.x & 31;
    if (w >= NN) return;
    int beg = g_rowptr[w];
    int end = g_rowptr[w + 1];
    float4 acc = gather_sum_h(g_Xs_h, beg, end, lane);
    if (lane < 16) {
        float dinv = g_dinv[w];
        float rn = 2.0f / lambda_max[0];
        float a = -rn * dinv;
        float b = rn - 1.0f;
        float4 x0 = *(const float4*)(feat + (size_t)w * DD + lane * 4);
        float4 x1;
        x1.x = a * acc.x + b * x0.x;
        x1.y = a * acc.y + b * x0.y;
        x1.z = a * acc.z + b * x0.z;
        x1.w = a * acc.w + b * x0.w;
        *(float4*)(g_X1 + (size_t)w * DD + lane * 4) = x1;
        __half2 h0 = __float22half2_rn(make_float2(x1.x * dinv, x1.y * dinv));
        __half2 h1 = __float22half2_rn(make_float2(x1.z * dinv, x1.w * dinv));
        uint2 packed = make_uint2(h2_bits(h0), h2_bits(h1));
        *(uint2*)((char*)g_X1s_h + (size_t)w * 128 + lane * 8) = packed;
        *(float4*)(out + (size_t)w * OUTD + DD + lane * 4) =
            make_float4(fmaxf(x1.x, 0.f), fmaxf(x1.y, 0.f),
                        fmaxf(x1.z, 0.f), fmaxf(x1.w, 0.f));
    }
}

// pass 2: h2 = dinv * sum(X1s[col]); X2 = -2*rn*h2 + 2*(rn-1)*X1 - X0
// writes out[:, 128:192] = relu(X2). X1 term uses the exact fp32 buffer.
__global__ void k_spmm2(const float* __restrict__ feat,
                        const float* __restrict__ lambda_max,
                        float* __restrict__ out) {
    int w = (blockIdx.x * blockDim.x + threadIdx.x) >> 5;
    int lane = threadIdx.x & 31;
    if (w >= NN) return;
    int beg = g_rowptr[w];
    int end = g_rowptr[w + 1];
    float4 acc = gather_sum_h(g_X1s_h, beg, end, lane);
    if (lane < 16) {
        float dinv = g_dinv[w];
        float rn = 2.0f / lambda_max[0];
        float a = -2.0f * rn * dinv;
        float b = 2.0f * (rn - 1.0f);
        float4 x0 = *(const float4*)(feat + (size_t)w * DD + lane * 4);
        float4 x1 = *(const float4*)(g_X1 + (size_t)w * DD + lane * 4);
        float4 x2;
        x2.x = a * acc.x + b * x1.x - x0.x;
        x2.y = a * acc.y + b * x1.y - x0.y;
        x2.z = a * acc.z + b * x1.z - x0.z;
        x2.w = a * acc.w + b * x1.w - x0.w;
        *(float4*)(out + (size_t)w * OUTD + 2 * DD + lane * 4) =
            make_float4(fmaxf(x2.x, 0.f), fmaxf(x2.y, 0.f),
                        fmaxf(x2.z, 0.f), fmaxf(x2.w, 0.f));
    }
}

extern "C" void kernel_launch(void* const* d_in, const int* in_sizes, int n_in,
                              void* d_out, int out_size) {
    const float* feat       = (const float*)d_in[0];
    const int*   src        = (const int*)d_in[1];
    const int*   dst        = (const int*)d_in[2];
    const float* lambda_max = (const float*)d_in[3];
    float* out = (float*)d_out;

    const int TB = 256;
    k_zero_deg<<<(NN + TB - 1) / TB, TB>>>();
    k_deg<<<(EE + TB - 1) / TB, TB>>>(dst);
    k_scan<<<1, 1024>>>();
    k_prep<<<(NN * 16 + TB - 1) / TB, TB>>>(feat, out);
    k_fill<<<(EE + TB - 1) / TB, TB>>>(src, dst);
    k_spmm1<<<(NN * 32 + TB - 1) / TB, TB>>>(feat, lambda_max, out);
    k_spmm2<<<(NN * 32 + TB - 1) / TB, TB>>>(feat, lambda_max, out);
}